// round 4
// baseline (speedup 1.0000x reference)
#include <cuda_runtime.h>

#define NN 50000
#define EE 640000
#define HH 128
#define GG 128
#define FN 64
#define FEDGE 16
#define FLIG 200
#define FPOC 100
#define NPB 64                      // nodes per block
#define RL 148                      // shared row length (floats), %4==0
#define NBLK ((NN + NPB - 1) / NPB) // 782

// ---- scratch (zero-initialized at load; graph is self-restoring) ----
__device__ int   g_counts[NN];   // reset by k_fill
__device__ int   g_fill[NN];     // reset by k_conv1
__device__ int   g_rowptr[NN + 1];
__device__ int   g_src[EE];
__device__ int   g_eid[EE];
__device__ float g_h0[NN * HH];
__device__ float g_h1[NN * HH];
__device__ float g_aedge[NN * FEDGE];
__device__ float g_pool[GG * HH];

typedef unsigned long long ull;

__device__ __forceinline__ ull pk2(float lo, float hi) {
    ull r; asm("mov.b64 %0, {%1, %2};" : "=l"(r) : "f"(lo), "f"(hi)); return r;
}
__device__ __forceinline__ float2 upk2(ull v) {
    float2 r; asm("mov.b64 {%0, %1}, %2;" : "=f"(r.x), "=f"(r.y) : "l"(v)); return r;
}
__device__ __forceinline__ void fma2(ull& acc, ull a, ull b) {
    asm("fma.rn.f32x2 %0, %1, %2, %0;" : "+l"(acc) : "l"(a), "l"(b));
}
__device__ __forceinline__ void add4(float4& a, float4 b) {
    a.x += b.x; a.y += b.y; a.z += b.z; a.w += b.w;
}
__device__ __forceinline__ int lbound(const int* __restrict__ arr, int n, int v) {
    int lo = 0, hi = n;
    while (lo < hi) { int m = (lo + hi) >> 1; if (arr[m] < v) lo = m + 1; else hi = m; }
    return lo;
}

// ---- CSR build ----
__global__ void k_count(const int* __restrict__ ei) {
    int t = blockIdx.x * blockDim.x + threadIdx.x;
    if (t >= EE / 4) return;
    int4 d = ((const int4*)(ei + EE))[t];
    atomicAdd(&g_counts[d.x], 1);
    atomicAdd(&g_counts[d.y], 1);
    atomicAdd(&g_counts[d.z], 1);
    atomicAdd(&g_counts[d.w], 1);
}

__global__ void k_scan() {
    __shared__ int ss[1024];
    int t = threadIdx.x;
    const int chunk = (NN + 1023) / 1024;
    int start = t * chunk;
    int end = min(start + chunk, NN);
    int s = 0;
    for (int i = start; i < end; i++) s += g_counts[i];
    ss[t] = s;
    __syncthreads();
    for (int off = 1; off < 1024; off <<= 1) {
        int v = (t >= off) ? ss[t - off] : 0;
        __syncthreads();
        ss[t] += v;
        __syncthreads();
    }
    int run = (t == 0) ? 0 : ss[t - 1];
    for (int i = start; i < end; i++) { g_rowptr[i] = run; run += g_counts[i]; }
    if (t == 1023) g_rowptr[NN] = ss[1023];
}

__global__ void k_fill(const int* __restrict__ ei) {
    int t = blockIdx.x * blockDim.x + threadIdx.x;
    if (t >= EE / 4) return;
    int4 d = ((const int4*)(ei + EE))[t];
    int4 s = ((const int4*)ei)[t];
    int e = 4 * t;
    int p;
    p = g_rowptr[d.x] + atomicAdd(&g_fill[d.x], 1); g_src[p] = s.x; g_eid[p] = e;
    p = g_rowptr[d.y] + atomicAdd(&g_fill[d.y], 1); g_src[p] = s.y; g_eid[p] = e + 1;
    p = g_rowptr[d.z] + atomicAdd(&g_fill[d.z], 1); g_src[p] = s.z; g_eid[p] = e + 2;
    p = g_rowptr[d.w] + atomicAdd(&g_fill[d.w], 1); g_src[p] = s.w; g_eid[p] = e + 3;
    g_counts[d.x] = 0; g_counts[d.y] = 0; g_counts[d.z] = 0; g_counts[d.w] = 0;
}

// ---- conv1: gather (ax|xn|ae) into sR, then register-tiled f32x2 GEMM ----
__global__ void __launch_bounds__(256) k_conv1(
        const float* __restrict__ x, const float* __restrict__ ea,
        const float* __restrict__ Wm, const float* __restrict__ bm,
        const float* __restrict__ We, const float* __restrict__ be,
        const float* __restrict__ Ws, const float* __restrict__ bs) {
    __shared__ __align__(16) float sR[NPB][RL];
    __shared__ float sdeg[NPB];
    int tid = threadIdx.x, warp = tid >> 5, lane = tid & 31;
    int n0 = blockIdx.x * NPB;

    if (tid < NPB) { int n = n0 + tid; if (n < NN) g_fill[n] = 0; }

    const float4* xb = (const float4*)x;
    int half = lane >> 4, hl = lane & 15, q = lane & 3;
    #pragma unroll 1
    for (int i = 0; i < NPB / 8; i++) {
        int nl = warp * (NPB / 8) + i;
        int n = min(n0 + nl, NN - 1);
        int beg = g_rowptr[n], end = g_rowptr[n + 1];
        // ---- ax: 2 edges per step (half-warps), 2-deep unroll ----
        float4 a0 = make_float4(0.f, 0.f, 0.f, 0.f), a1 = a0;
        int s = beg;
        for (; s + 3 < end; s += 4) {
            add4(a0, xb[g_src[s + half] * (FN / 4) + hl]);
            add4(a1, xb[g_src[s + 2 + half] * (FN / 4) + hl]);
        }
        for (; s + 1 < end; s += 2) add4(a0, xb[g_src[s + half] * (FN / 4) + hl]);
        if (s < end && half == 0) add4(a0, xb[g_src[s] * (FN / 4) + hl]);
        add4(a0, a1);
        a0.x += __shfl_xor_sync(0xffffffffu, a0.x, 16);
        a0.y += __shfl_xor_sync(0xffffffffu, a0.y, 16);
        a0.z += __shfl_xor_sync(0xffffffffu, a0.z, 16);
        a0.w += __shfl_xor_sync(0xffffffffu, a0.w, 16);
        if (half == 0) *(float4*)&sR[nl][4 * hl] = a0;
        else           *(float4*)&sR[nl][FN + 4 * hl] = xb[n * (FN / 4) + hl];
        if (lane == 0) sdeg[nl] = (float)(end - beg);
        // ---- ae: 8 edges per step ----
        float4 ac = make_float4(0.f, 0.f, 0.f, 0.f);
        for (int t2 = beg; t2 < end; t2 += 8) {
            int e = t2 + (lane >> 2);
            if (e < end) add4(ac, ((const float4*)ea)[g_eid[e] * 4 + q]);
        }
        #pragma unroll
        for (int m = 4; m <= 16; m <<= 1) {
            ac.x += __shfl_xor_sync(0xffffffffu, ac.x, m);
            ac.y += __shfl_xor_sync(0xffffffffu, ac.y, m);
            ac.z += __shfl_xor_sync(0xffffffffu, ac.z, m);
            ac.w += __shfl_xor_sync(0xffffffffu, ac.w, m);
        }
        if (lane < 4) {
            *(float4*)&sR[nl][2 * FN + 4 * q] = ac;
            ((float4*)(g_aedge + n * FEDGE))[q] = ac;
        }
    }
    __syncthreads();

    // ---- GEMM: thread (rg,cg) -> rows r0..r0+3, cols c0..c0+7 ----
    int rg = tid >> 4, cg = tid & 15;
    int r0 = rg * 4, c0 = cg * 8;
    float4 bmA = *(const float4*)&bm[c0], bmB = *(const float4*)&bm[c0 + 4];
    float4 beA = *(const float4*)&be[c0], beB = *(const float4*)&be[c0 + 4];
    float4 bsA = *(const float4*)&bs[c0], bsB = *(const float4*)&bs[c0 + 4];
    float bb[8] = {bmA.x + beA.x, bmA.y + beA.y, bmA.z + beA.z, bmA.w + beA.w,
                   bmB.x + beB.x, bmB.y + beB.y, bmB.z + beB.z, bmB.w + beB.w};
    float bss[8] = {bsA.x, bsA.y, bsA.z, bsA.w, bsB.x, bsB.y, bsB.z, bsB.w};
    ull acc[4][4];
    #pragma unroll
    for (int r = 0; r < 4; r++) {
        float dg = sdeg[r0 + r];
        acc[r][0] = pk2(bss[0] + dg * bb[0], bss[1] + dg * bb[1]);
        acc[r][1] = pk2(bss[2] + dg * bb[2], bss[3] + dg * bb[3]);
        acc[r][2] = pk2(bss[4] + dg * bb[4], bss[5] + dg * bb[5]);
        acc[r][3] = pk2(bss[6] + dg * bb[6], bss[7] + dg * bb[7]);
    }
    #pragma unroll 2
    for (int k = 0; k < FN; k++) {
        float4 wa = *(const float4*)&Wm[k * HH + c0];
        float4 wb = *(const float4*)&Wm[k * HH + c0 + 4];
        float4 ua = *(const float4*)&Ws[k * HH + c0];
        float4 ub = *(const float4*)&Ws[k * HH + c0 + 4];
        ull w0 = pk2(wa.x, wa.y), w1 = pk2(wa.z, wa.w);
        ull w2 = pk2(wb.x, wb.y), w3 = pk2(wb.z, wb.w);
        ull u0 = pk2(ua.x, ua.y), u1 = pk2(ua.z, ua.w);
        ull u2 = pk2(ub.x, ub.y), u3 = pk2(ub.z, ub.w);
        #pragma unroll
        for (int r = 0; r < 4; r++) {
            ull pa = pk2(sR[r0 + r][k], sR[r0 + r][k]);
            ull px = pk2(sR[r0 + r][FN + k], sR[r0 + r][FN + k]);
            fma2(acc[r][0], pa, w0); fma2(acc[r][1], pa, w1);
            fma2(acc[r][2], pa, w2); fma2(acc[r][3], pa, w3);
            fma2(acc[r][0], px, u0); fma2(acc[r][1], px, u1);
            fma2(acc[r][2], px, u2); fma2(acc[r][3], px, u3);
        }
    }
    #pragma unroll 2
    for (int k = 0; k < FEDGE; k++) {
        float4 wa = *(const float4*)&We[k * HH + c0];
        float4 wb = *(const float4*)&We[k * HH + c0 + 4];
        ull w0 = pk2(wa.x, wa.y), w1 = pk2(wa.z, wa.w);
        ull w2 = pk2(wb.x, wb.y), w3 = pk2(wb.z, wb.w);
        #pragma unroll
        for (int r = 0; r < 4; r++) {
            ull pa = pk2(sR[r0 + r][2 * FN + k], sR[r0 + r][2 * FN + k]);
            fma2(acc[r][0], pa, w0); fma2(acc[r][1], pa, w1);
            fma2(acc[r][2], pa, w2); fma2(acc[r][3], pa, w3);
        }
    }
    #pragma unroll
    for (int r = 0; r < 4; r++) {
        int n = n0 + r0 + r;
        if (n < NN) {
            float2 v0 = upk2(acc[r][0]), v1 = upk2(acc[r][1]);
            float2 v2 = upk2(acc[r][2]), v3 = upk2(acc[r][3]);
            float4 oA = make_float4(fmaxf(v0.x, 0.f), fmaxf(v0.y, 0.f),
                                    fmaxf(v1.x, 0.f), fmaxf(v1.y, 0.f));
            float4 oB = make_float4(fmaxf(v2.x, 0.f), fmaxf(v2.y, 0.f),
                                    fmaxf(v3.x, 0.f), fmaxf(v3.y, 0.f));
            *(float4*)&g_h0[n * HH + c0] = oA;
            *(float4*)&g_h0[n * HH + c0 + 4] = oB;
        }
    }
}

// ---- stacked layer: gather (ah|ae) into sR + register-tiled f32x2 GEMM ----
__global__ void __launch_bounds__(256) k_layer(int l,
        const float* __restrict__ Wkm, const float* __restrict__ bkm,
        const float* __restrict__ Wke, const float* __restrict__ bke) {
    const float* __restrict__ hin = (l & 1) ? g_h1 : g_h0;
    float* __restrict__ hout      = (l & 1) ? g_h0 : g_h1;
    const float* __restrict__ Wm = Wkm + l * HH * HH;
    const float* __restrict__ bm = bkm + l * HH;
    const float* __restrict__ We = Wke + l * FEDGE * HH;
    const float* __restrict__ be = bke + l * HH;

    __shared__ __align__(16) float sR[NPB][RL];
    __shared__ float sdeg[NPB];
    int tid = threadIdx.x, warp = tid >> 5, lane = tid & 31;
    int n0 = blockIdx.x * NPB;

    const float4* hb = (const float4*)hin;
    #pragma unroll 1
    for (int i = 0; i < NPB / 8; i++) {
        int nl = warp * (NPB / 8) + i;
        int n = min(n0 + nl, NN - 1);
        int beg = g_rowptr[n], end = g_rowptr[n + 1];
        float4 a0 = make_float4(0.f, 0.f, 0.f, 0.f), a1 = a0, a2 = a0, a3 = a0;
        int s = beg;
        for (; s + 3 < end; s += 4) {
            add4(a0, hb[g_src[s] * (HH / 4) + lane]);
            add4(a1, hb[g_src[s + 1] * (HH / 4) + lane]);
            add4(a2, hb[g_src[s + 2] * (HH / 4) + lane]);
            add4(a3, hb[g_src[s + 3] * (HH / 4) + lane]);
        }
        for (; s < end; s++) add4(a0, hb[g_src[s] * (HH / 4) + lane]);
        add4(a0, a1); add4(a2, a3); add4(a0, a2);
        *(float4*)&sR[nl][4 * lane] = a0;
        if (lane == 0) sdeg[nl] = (float)(end - beg);
        if (lane < 4)
            *(float4*)&sR[nl][HH + 4 * lane] = ((const float4*)(g_aedge + n * FEDGE))[lane];
    }
    __syncthreads();

    int rg = tid >> 4, cg = tid & 15;
    int r0 = rg * 4, c0 = cg * 8;
    float4 bmA = *(const float4*)&bm[c0], bmB = *(const float4*)&bm[c0 + 4];
    float4 beA = *(const float4*)&be[c0], beB = *(const float4*)&be[c0 + 4];
    float bb[8] = {bmA.x + beA.x, bmA.y + beA.y, bmA.z + beA.z, bmA.w + beA.w,
                   bmB.x + beB.x, bmB.y + beB.y, bmB.z + beB.z, bmB.w + beB.w};
    ull acc[4][4];
    #pragma unroll
    for (int r = 0; r < 4; r++) {
        int n = min(n0 + r0 + r, NN - 1);
        float4 s0 = *(const float4*)&hin[n * HH + c0];
        float4 s1 = *(const float4*)&hin[n * HH + c0 + 4];
        float dg = sdeg[r0 + r];
        acc[r][0] = pk2(s0.x + dg * bb[0], s0.y + dg * bb[1]);
        acc[r][1] = pk2(s0.z + dg * bb[2], s0.w + dg * bb[3]);
        acc[r][2] = pk2(s1.x + dg * bb[4], s1.y + dg * bb[5]);
        acc[r][3] = pk2(s1.z + dg * bb[6], s1.w + dg * bb[7]);
    }
    #pragma unroll 4
    for (int k = 0; k < HH; k++) {
        float4 wa = *(const float4*)&Wm[k * HH + c0];
        float4 wb = *(const float4*)&Wm[k * HH + c0 + 4];
        ull w0 = pk2(wa.x, wa.y), w1 = pk2(wa.z, wa.w);
        ull w2 = pk2(wb.x, wb.y), w3 = pk2(wb.z, wb.w);
        #pragma unroll
        for (int r = 0; r < 4; r++) {
            ull pa = pk2(sR[r0 + r][k], sR[r0 + r][k]);
            fma2(acc[r][0], pa, w0); fma2(acc[r][1], pa, w1);
            fma2(acc[r][2], pa, w2); fma2(acc[r][3], pa, w3);
        }
    }
    #pragma unroll 2
    for (int k = 0; k < FEDGE; k++) {
        float4 wa = *(const float4*)&We[k * HH + c0];
        float4 wb = *(const float4*)&We[k * HH + c0 + 4];
        ull w0 = pk2(wa.x, wa.y), w1 = pk2(wa.z, wa.w);
        ull w2 = pk2(wb.x, wb.y), w3 = pk2(wb.z, wb.w);
        #pragma unroll
        for (int r = 0; r < 4; r++) {
            ull pa = pk2(sR[r0 + r][HH + k], sR[r0 + r][HH + k]);
            fma2(acc[r][0], pa, w0); fma2(acc[r][1], pa, w1);
            fma2(acc[r][2], pa, w2); fma2(acc[r][3], pa, w3);
        }
    }
    #pragma unroll
    for (int r = 0; r < 4; r++) {
        int n = n0 + r0 + r;
        if (n < NN) {
            float2 v0 = upk2(acc[r][0]), v1 = upk2(acc[r][1]);
            float2 v2 = upk2(acc[r][2]), v3 = upk2(acc[r][3]);
            float4 oA = make_float4(fmaxf(v0.x, 0.f), fmaxf(v0.y, 0.f),
                                    fmaxf(v1.x, 0.f), fmaxf(v1.y, 0.f));
            float4 oB = make_float4(fmaxf(v2.x, 0.f), fmaxf(v2.y, 0.f),
                                    fmaxf(v3.x, 0.f), fmaxf(v3.y, 0.f));
            *(float4*)&hout[n * HH + c0] = oA;
            *(float4*)&hout[n * HH + c0 + 4] = oB;
        }
    }
}

// ---- mean pool: batch sorted -> binary-search segment, no atomics ----
__global__ void __launch_bounds__(256) k_pool(const int* __restrict__ batch) {
    int g = blockIdx.x;
    int tid = threadIdx.x;
    int j = tid & 127, half = tid >> 7;
    int lo = lbound(batch, NN, g);
    int hi = lbound(batch, NN, g + 1);
    float a = 0.f, b = 0.f;
    int n = lo + half;
    for (; n + 3 < hi; n += 4) {
        a += g_h1[n * HH + j];
        b += g_h1[(n + 2) * HH + j];
    }
    for (; n < hi; n += 2) a += g_h1[n * HH + j];
    __shared__ float red[256];
    red[tid] = a + b;
    __syncthreads();
    if (half == 0) {
        float s = red[j] + red[j + 128];
        float c = (float)(hi - lo);
        g_pool[g * HH + j] = s / fmaxf(c, 1.f);
    }
}

// ---- head ----
__global__ void k_head(const float* __restrict__ lig, const float* __restrict__ poc,
                       const float* __restrict__ Wl, const float* __restrict__ bl,
                       const float* __restrict__ Wp, const float* __restrict__ bp,
                       const float* __restrict__ Wf, const float* __restrict__ bf,
                       const float* __restrict__ Wo, const float* __restrict__ bo,
                       float* __restrict__ out) {
    int g = blockIdx.x, j = threadIdx.x;
    __shared__ float f[3 * HH];
    __shared__ float o[HH];
    f[j] = g_pool[g * HH + j];
    float a = bl[j];
    #pragma unroll 4
    for (int k = 0; k < FLIG; k++) a += lig[g * FLIG + k] * Wl[k * HH + j];
    f[HH + j] = a;
    float b = bp[j];
    #pragma unroll 4
    for (int k = 0; k < FPOC; k++) b += poc[g * FPOC + k] * Wp[k * HH + j];
    f[2 * HH + j] = b;
    __syncthreads();
    float acc = bf[j];
    #pragma unroll 8
    for (int k = 0; k < 3 * HH; k++) acc += f[k] * Wf[k * HH + j];
    o[j] = acc * Wo[j];
    __syncthreads();
    for (int s = 64; s > 0; s >>= 1) {
        if (j < s) o[j] += o[j + s];
        __syncthreads();
    }
    if (j == 0) out[g] = o[0] + bo[0];
}

extern "C" void kernel_launch(void* const* d_in, const int* in_sizes, int n_in,
                              void* d_out, int out_size) {
    const float* x    = (const float*)d_in[0];
    const int*   ei   = (const int*)d_in[1];
    const float* ea   = (const float*)d_in[2];
    const int*   batch= (const int*)d_in[3];
    const float* lig  = (const float*)d_in[4];
    const float* poc  = (const float*)d_in[5];
    const float* W1m  = (const float*)d_in[6];
    const float* b1m  = (const float*)d_in[7];
    const float* W1e  = (const float*)d_in[8];
    const float* b1e  = (const float*)d_in[9];
    const float* W1s  = (const float*)d_in[10];
    const float* b1s  = (const float*)d_in[11];
    const float* Wkm  = (const float*)d_in[12];
    const float* bkm  = (const float*)d_in[13];
    const float* Wke  = (const float*)d_in[14];
    const float* bke  = (const float*)d_in[15];
    const float* Wl   = (const float*)d_in[16];
    const float* bl   = (const float*)d_in[17];
    const float* Wp   = (const float*)d_in[18];
    const float* bp   = (const float*)d_in[19];
    const float* Wf   = (const float*)d_in[20];
    const float* bf   = (const float*)d_in[21];
    const float* Wo   = (const float*)d_in[22];
    const float* bo   = (const float*)d_in[23];
    float* out = (float*)d_out;

    k_count<<<(EE / 4 + 255) / 256, 256>>>(ei);
    k_scan <<<1, 1024>>>();
    k_fill <<<(EE / 4 + 255) / 256, 256>>>(ei);
    k_conv1<<<NBLK, 256>>>(x, ea, W1m, b1m, W1e, b1e, W1s, b1s);
    for (int l = 0; l < 3; l++)
        k_layer<<<NBLK, 256>>>(l, Wkm, bkm, Wke, bke);
    k_pool <<<GG, 256>>>(batch);
    k_head <<<GG, HH>>>(lig, poc, Wl, bl, Wp, bp, Wf, bf, Wo, bo, out);
}